// round 14
// baseline (speedup 1.0000x reference)
#include <cuda_runtime.h>
#include <cstdint>

#define RCUT 5.2f
#define WPB 2
#define SEG_CAP 288                // 255 valid + up to 7 pads x 4 segments
#define NK (-23.083120654223414f)  // -eta/ln2, eta=16
#define PI_RC 0.604152403831652f   // pi / 5.2

__device__ __forceinline__ float ex2_approx(float x) {
    float r; asm("ex2.approx.f32 %0, %1;" : "=f"(r) : "f"(x)); return r;
}
__device__ __forceinline__ float cos_approx(float x) {
    float r; asm("cos.approx.f32 %0, %1;" : "=f"(r) : "f"(x)); return r;
}
// Predicated vector shared store — no branch envelope.
__device__ __forceinline__ void sts_v2_pred(uint32_t pred, uint32_t addr,
                                            float x, float y) {
    asm volatile("{ .reg .pred p; setp.ne.u32 p, %0, 0;\n\t"
                 "@p st.shared.v2.f32 [%1], {%2, %3}; }"
                 :: "r"(pred), "r"(addr), "f"(x), "f"(y));
}

// Sum one species segment; len is a multiple of 8 (padded with fc=0 entries).
// AoS float2. Lanes 0-15 take pairs {kk,kk+1},{kk+4,kk+5}; lanes 16-31 rest.
__device__ __forceinline__ float seg_accum(const float2* __restrict__ s,
                                           int len, int half2,
                                           float A, float C) {
    float accA = 0.0f, accB = 0.0f;
    const float4* __restrict__ p = (const float4*)(s + half2);
    for (int kk = 0; kk < len; kk += 8) {
        float4 a = p[kk >> 1];
        float4 b = p[(kk >> 1) + 2];
        float y0 = fmaf(fmaf(NK, a.x, A), a.x, C);
        float y1 = fmaf(fmaf(NK, a.z, A), a.z, C);
        float y2 = fmaf(fmaf(NK, b.x, A), b.x, C);
        float y3 = fmaf(fmaf(NK, b.z, A), b.z, C);
        accA = fmaf(ex2_approx(y0), a.y, accA);
        accB = fmaf(ex2_approx(y1), a.w, accB);
        accA = fmaf(ex2_approx(y2), b.y, accA);
        accB = fmaf(ex2_approx(y3), b.w, accB);
    }
    return accA + accB;
}

// Fast path: N == 256.
// minBlocks=24 -> 42-reg budget: room for the natural ~36-40 live values,
// eliminating the forced-32-reg spill regime of the minBlocks=28 builds.
__global__ __launch_bounds__(32 * WPB, 24)
void radial_aev_256(const float* __restrict__ dmat,
                    const int*   __restrict__ species,
                    float*       __restrict__ out)
{
    __shared__ alignas(16) float2 sh[WPB][SEG_CAP];
    __shared__ uint32_t ssp[64];   // packed bytes: ((species-1)<<4) per j

    const int warp = threadIdx.x >> 5;
    const int lane = threadIdx.x & 31;
    const int row  = blockIdx.x * WPB + warp;
    const int brow = (blockIdx.x * WPB) >> 8;   // same batch for whole block

    // ---- block-cooperative species preprocess (64 threads = whole row) ----
    {
        int4 sv = ((const int4*)(species + (size_t)brow * 256))[threadIdx.x];
        uint32_t w =  (uint32_t)((sv.x - 1) << 4)
                   | ((uint32_t)((sv.y - 1) << 4) << 8)
                   | ((uint32_t)((sv.z - 1) << 4) << 16)
                   | ((uint32_t)((sv.w - 1) << 4) << 24);
        ssp[threadIdx.x] = w;
    }
    __syncthreads();

    // ---- Phase 1: lane owns j = 8*lane .. 8*lane+7 ----
    const float* __restrict__ drow = dmat + (size_t)row * 256;
    float4 a = ((const float4*)drow)[lane * 2];
    float4 b = ((const float4*)drow)[lane * 2 + 1];
    float dv[8] = {a.x, a.y, a.z, a.w, b.x, b.y, b.z, b.w};

    const uint32_t u0 = ssp[lane * 2], u1 = ssp[lane * 2 + 1];

    // validity (0<d<RC  <=>  d*(RC-d)>0) + packed 8-bit per-species counts
    uint32_t vvi[8];
    uint32_t cpk = 0;
    #pragma unroll
    for (int e = 0; e < 8; e++) {
        uint32_t v = (dv[e] * (RCUT - dv[e]) > 0.0f) ? 1u : 0u;
        vvi[e] = v;
        uint32_t uw = (e < 4) ? u0 : u1;
        int s16 = (uw >> (8 * (e & 3))) & 0xff;    // (sp-1)<<4
        cpk += v << (s16 >> 1);                     // shift in {0,8,16,24}
    }

    // single packed inclusive scan (8-bit fields, counts <= 255: no carry)
    uint32_t ipk = cpk;
    #pragma unroll
    for (int o = 1; o < 32; o <<= 1) {
        uint32_t n = __shfl_up_sync(0xffffffffu, ipk, o);
        if (lane >= o) ipk += n;
    }
    const uint32_t tot = __shfl_sync(0xffffffffu, ipk, 31);
    const uint32_t epk = ipk - cpk;                // exclusive, packed

    const int T0 = tot & 0xff, T1 = (tot >> 8) & 0xff;
    const int T2 = (tot >> 16) & 0xff, T3 = tot >> 24;
    const int L0 = (T0 + 7) & ~7, L1 = (T1 + 7) & ~7;
    const int L2 = (T2 + 7) & ~7, L3 = (T3 + 7) & ~7;
    const int B1 = L0, B2 = L0 + L1, B3 = L0 + L1 + L2;

    // packed 16-bit cursors with bases folded in
    uint32_t rlo = (epk & 0xff)                | ((B1 + ((epk >> 8)  & 0xff)) << 16);
    uint32_t rhi = (B2 + ((epk >> 16) & 0xff)) | ((B3 + (epk >> 24))          << 16);

    const uint32_t base_u32 =
        (uint32_t)__cvta_generic_to_shared(&sh[warp][0]);

    #pragma unroll
    for (int e = 0; e < 8; e++) {
        float d  = dv[e];
        float fc = fmaf(cos_approx(d * PI_RC), 0.5f, 0.5f);
        uint32_t uw = (e < 4) ? u0 : u1;
        int s16 = (uw >> (8 * (e & 3))) & 0xff;
        int hi  = s16 & 32;
        int sh16 = s16 & 16;
        uint32_t rp = hi ? rhi : rlo;
        uint32_t pos = (rp >> sh16) & 0xffffu;
        sts_v2_pred(vvi[e], base_u32 + pos * 8u, d, fc);   // 0-BSSY store
        uint32_t inc = vvi[e] << sh16;
        rlo += hi ? 0u : inc;                       // SEL, no branch
        rhi += hi ? inc : 0u;
    }

    // pad tails (disjoint from scatter region — no sync needed in between):
    // lane -> (segment = lane>>3, k = lane&7), predicated store
    {
        int s = lane >> 3, k = lane & 7;
        int Ts = (tot >> (8 * s)) & 0xff;
        int Bs = (s == 0) ? 0 : (s == 1) ? B1 : (s == 2) ? B2 : B3;
        int Ls = (Ts + 7) & ~7;
        uint32_t need = (Ts + k < Ls) ? 1u : 0u;
        sts_v2_pred(need, base_u32 + (uint32_t)(Bs + Ts + k) * 8u, 1.0f, 0.0f);
    }
    __syncwarp();

    // ---- Phase 2: lane = (p = lane&15, pair-half = lane>>4) ----
    const float shf = fmaf((float)(lane & 15), 0.26875f, 0.9f);
    const float A   = -2.0f * NK * shf;
    const float C   = NK * shf * shf;
    const int   half2 = (lane >> 4) << 1;
    const float2* __restrict__ basep = sh[warp];

    float acc0 = seg_accum(basep,      L0, half2, A, C);
    float acc1 = seg_accum(basep + B1, L1, half2, A, C);
    float acc2 = seg_accum(basep + B2, L2, half2, A, C);
    float acc3 = seg_accum(basep + B3, L3, half2, A, C);

    acc0 += __shfl_xor_sync(0xffffffffu, acc0, 16);
    acc1 += __shfl_xor_sync(0xffffffffu, acc1, 16);
    acc2 += __shfl_xor_sync(0xffffffffu, acc2, 16);
    acc3 += __shfl_xor_sync(0xffffffffu, acc3, 16);

    // all 32 lanes store: lanes 0-15 write s0/s1, lanes 16-31 write s2/s3
    {
        float* orow = out + (size_t)row * 64;
        int  l15  = lane & 15;
        bool lo16 = lane < 16;
        int  off  = lo16 ? l15 : (32 + l15);
        orow[off]      = lo16 ? acc0 : acc2;
        orow[off + 16] = lo16 ? acc1 : acc3;
    }
}

// Generic fallback (any N): one 64-thread block per row, direct evaluation.
__global__ void radial_aev_generic(const float* __restrict__ dmat,
                                   const int*   __restrict__ species,
                                   float*       __restrict__ out,
                                   int N, int rows)
{
    int row = blockIdx.x;
    if (row >= rows) return;
    int t = threadIdx.x;            // 64 threads: s = t>>4, p = t&15
    int s = t >> 4, p = t & 15;
    float shf = fmaf((float)p, 0.26875f, 0.9f);
    const float* drow = dmat + (size_t)row * N;
    const int*   srow = species + (size_t)(row / N) * N;
    float acc = 0.0f;
    for (int j = 0; j < N; j++) {
        float d = drow[j];
        if (d > 0.0f && d < RCUT && (srow[j] - 1) == s) {
            float fc = 0.5f * __cosf(d * PI_RC) + 0.5f;
            float tt = d - shf;
            acc += __expf(-16.0f * tt * tt) * fc;
        }
    }
    out[(size_t)row * 64 + t] = acc;
}

extern "C" void kernel_launch(void* const* d_in, const int* in_sizes, int n_in,
                              void* d_out, int out_size)
{
    const float* dmat    = (const float*)d_in[0];
    const int*   species = (const int*)d_in[1];
    float*       out     = (float*)d_out;

    const int rows = in_sizes[1];                 // B*N
    const int N    = in_sizes[0] / in_sizes[1];   // N

    if (N == 256 && (rows & (WPB - 1)) == 0 && (rows & 255) == 0) {
        radial_aev_256<<<rows / WPB, 32 * WPB>>>(dmat, species, out);
    } else {
        radial_aev_generic<<<rows, 64>>>(dmat, species, out, N, rows);
    }
}

// round 16
// speedup vs baseline: 1.1347x; 1.1347x over previous
#include <cuda_runtime.h>
#include <cstdint>

#define RCUT 5.2f
#define WPB 2
#define SEG_CAP 288                // 255 valid + up to 7 pads x 4 segments
#define NK (-23.083120654223414f)  // -eta/ln2, eta=16
#define PI_RC 0.604152403831652f   // pi / 5.2

__device__ __forceinline__ float ex2_approx(float x) {
    float r; asm("ex2.approx.f32 %0, %1;" : "=f"(r) : "f"(x)); return r;
}
__device__ __forceinline__ float cos_approx(float x) {
    float r; asm("cos.approx.f32 %0, %1;" : "=f"(r) : "f"(x)); return r;
}
// Predicated vector shared store — no branch envelope.
__device__ __forceinline__ void sts_v2_pred(uint32_t pred, uint32_t addr,
                                            float x, float y) {
    asm volatile("{ .reg .pred p; setp.ne.u32 p, %0, 0;\n\t"
                 "@p st.shared.v2.f32 [%1], {%2, %3}; }"
                 :: "r"(pred), "r"(addr), "f"(x), "f"(y));
}

// Fast path: N == 256.  (minBlocks=28 -> 32-reg compile: best measured config)
__global__ __launch_bounds__(32 * WPB, 28)
void radial_aev_256(const float* __restrict__ dmat,
                    const int*   __restrict__ species,
                    float*       __restrict__ out)
{
    __shared__ alignas(16) float2 sh[WPB][SEG_CAP];
    __shared__ uint32_t ssp[64];   // packed bytes: ((species-1)<<4) per j

    const int warp = threadIdx.x >> 5;
    const int lane = threadIdx.x & 31;
    const int row  = blockIdx.x * WPB + warp;
    const int brow = (blockIdx.x * WPB) >> 8;   // same batch for whole block

    // ---- block-cooperative species preprocess (64 threads = whole row) ----
    {
        int4 sv = ((const int4*)(species + (size_t)brow * 256))[threadIdx.x];
        uint32_t w =  (uint32_t)((sv.x - 1) << 4)
                   | ((uint32_t)((sv.y - 1) << 4) << 8)
                   | ((uint32_t)((sv.z - 1) << 4) << 16)
                   | ((uint32_t)((sv.w - 1) << 4) << 24);
        ssp[threadIdx.x] = w;
    }
    __syncthreads();

    // ---- Phase 1: lane owns j = 8*lane .. 8*lane+7 ----
    const float* __restrict__ drow = dmat + (size_t)row * 256;
    float4 a = ((const float4*)drow)[lane * 2];
    float4 b = ((const float4*)drow)[lane * 2 + 1];
    float dv[8] = {a.x, a.y, a.z, a.w, b.x, b.y, b.z, b.w};

    const uint32_t u0 = ssp[lane * 2], u1 = ssp[lane * 2 + 1];

    // validity (0<d<RC  <=>  d*(RC-d)>0) + packed 8-bit per-species counts
    uint32_t vvi[8];
    uint32_t cpk = 0;
    #pragma unroll
    for (int e = 0; e < 8; e++) {
        uint32_t v = (dv[e] * (RCUT - dv[e]) > 0.0f) ? 1u : 0u;
        vvi[e] = v;
        uint32_t uw = (e < 4) ? u0 : u1;
        int s16 = (uw >> (8 * (e & 3))) & 0xff;    // (sp-1)<<4
        cpk += v << (s16 >> 1);                     // shift in {0,8,16,24}
    }

    // single packed inclusive scan (8-bit fields, counts <= 255: no carry)
    uint32_t ipk = cpk;
    #pragma unroll
    for (int o = 1; o < 32; o <<= 1) {
        uint32_t n = __shfl_up_sync(0xffffffffu, ipk, o);
        if (lane >= o) ipk += n;
    }
    const uint32_t tot = __shfl_sync(0xffffffffu, ipk, 31);
    const uint32_t epk = ipk - cpk;                // exclusive, packed

    const int T0 = tot & 0xff, T1 = (tot >> 8) & 0xff;
    const int T2 = (tot >> 16) & 0xff, T3 = tot >> 24;
    const int L0 = (T0 + 7) & ~7, L1 = (T1 + 7) & ~7;
    const int L2 = (T2 + 7) & ~7, L3 = (T3 + 7) & ~7;
    const int B1 = L0, B2 = L0 + L1, B3 = L0 + L1 + L2;
    const int Lt = B3 + L3;

    // packed 16-bit cursors with bases folded in
    uint32_t rlo = (epk & 0xff)                | ((B1 + ((epk >> 8)  & 0xff)) << 16);
    uint32_t rhi = (B2 + ((epk >> 16) & 0xff)) | ((B3 + (epk >> 24))          << 16);

    const uint32_t base_u32 =
        (uint32_t)__cvta_generic_to_shared(&sh[warp][0]);

    #pragma unroll
    for (int e = 0; e < 8; e++) {
        float d  = dv[e];
        float fc = fmaf(cos_approx(d * PI_RC), 0.5f, 0.5f);
        uint32_t uw = (e < 4) ? u0 : u1;
        int s16 = (uw >> (8 * (e & 3))) & 0xff;
        int hi  = s16 & 32;
        int sh16 = s16 & 16;
        uint32_t rp = hi ? rhi : rlo;
        uint32_t pos = (rp >> sh16) & 0xffffu;
        sts_v2_pred(vvi[e], base_u32 + pos * 8u, d, fc);   // 0-BSSY store
        uint32_t inc = vvi[e] << sh16;
        rlo += hi ? 0u : inc;                       // SEL, no branch
        rhi += hi ? inc : 0u;
    }

    // pad tails (disjoint from scatter region — no sync needed in between):
    // lane -> (segment = lane>>3, k = lane&7), predicated store
    {
        int s = lane >> 3, k = lane & 7;
        int Ts = (tot >> (8 * s)) & 0xff;
        int Bs = (s == 0) ? 0 : (s == 1) ? B1 : (s == 2) ? B2 : B3;
        int Ls = (Ts + 7) & ~7;
        uint32_t need = (Ts + k < Ls) ? 1u : 0u;
        sts_v2_pred(need, base_u32 + (uint32_t)(Bs + Ts + k) * 8u, 1.0f, 0.0f);
    }
    __syncwarp();

    // ---- Phase 2: one continuous walk over all 4 segments, snapshots at
    // boundaries (all lengths are multiples of 8, so boundaries align).
    // Lanes 0-15 take pairs {kk,kk+1},{kk+4,kk+5}; lanes 16-31 the rest.
    const float shf = fmaf((float)(lane & 15), 0.26875f, 0.9f);
    const float A   = -2.0f * NK * shf;
    const float C   = NK * shf * shf;
    const int   half2 = (lane >> 4) << 1;
    const float4* __restrict__ p = (const float4*)(sh[warp] + half2);

    float accA = 0.0f, accB = 0.0f;
    int kk = 0;
    float s1A, s1B, s2A, s2B, s3A, s3B;

    #pragma unroll 1
    for (; kk < B1; kk += 8) {
        float4 va = p[kk >> 1];
        float4 vb = p[(kk >> 1) + 2];
        accA = fmaf(ex2_approx(fmaf(fmaf(NK, va.x, A), va.x, C)), va.y, accA);
        accB = fmaf(ex2_approx(fmaf(fmaf(NK, va.z, A), va.z, C)), va.w, accB);
        accA = fmaf(ex2_approx(fmaf(fmaf(NK, vb.x, A), vb.x, C)), vb.y, accA);
        accB = fmaf(ex2_approx(fmaf(fmaf(NK, vb.z, A), vb.z, C)), vb.w, accB);
    }
    s1A = accA; s1B = accB;
    #pragma unroll 1
    for (; kk < B2; kk += 8) {
        float4 va = p[kk >> 1];
        float4 vb = p[(kk >> 1) + 2];
        accA = fmaf(ex2_approx(fmaf(fmaf(NK, va.x, A), va.x, C)), va.y, accA);
        accB = fmaf(ex2_approx(fmaf(fmaf(NK, va.z, A), va.z, C)), va.w, accB);
        accA = fmaf(ex2_approx(fmaf(fmaf(NK, vb.x, A), vb.x, C)), vb.y, accA);
        accB = fmaf(ex2_approx(fmaf(fmaf(NK, vb.z, A), vb.z, C)), vb.w, accB);
    }
    s2A = accA; s2B = accB;
    #pragma unroll 1
    for (; kk < B3; kk += 8) {
        float4 va = p[kk >> 1];
        float4 vb = p[(kk >> 1) + 2];
        accA = fmaf(ex2_approx(fmaf(fmaf(NK, va.x, A), va.x, C)), va.y, accA);
        accB = fmaf(ex2_approx(fmaf(fmaf(NK, va.z, A), va.z, C)), va.w, accB);
        accA = fmaf(ex2_approx(fmaf(fmaf(NK, vb.x, A), vb.x, C)), vb.y, accA);
        accB = fmaf(ex2_approx(fmaf(fmaf(NK, vb.z, A), vb.z, C)), vb.w, accB);
    }
    s3A = accA; s3B = accB;
    #pragma unroll 1
    for (; kk < Lt; kk += 8) {
        float4 va = p[kk >> 1];
        float4 vb = p[(kk >> 1) + 2];
        accA = fmaf(ex2_approx(fmaf(fmaf(NK, va.x, A), va.x, C)), va.y, accA);
        accB = fmaf(ex2_approx(fmaf(fmaf(NK, va.z, A), va.z, C)), va.w, accB);
        accA = fmaf(ex2_approx(fmaf(fmaf(NK, vb.x, A), vb.x, C)), vb.y, accA);
        accB = fmaf(ex2_approx(fmaf(fmaf(NK, vb.z, A), vb.z, C)), vb.w, accB);
    }

    float acc0 = s1A + s1B;
    float acc1 = (s2A - s1A) + (s2B - s1B);
    float acc2 = (s3A - s2A) + (s3B - s2B);
    float acc3 = (accA - s3A) + (accB - s3B);

    acc0 += __shfl_xor_sync(0xffffffffu, acc0, 16);
    acc1 += __shfl_xor_sync(0xffffffffu, acc1, 16);
    acc2 += __shfl_xor_sync(0xffffffffu, acc2, 16);
    acc3 += __shfl_xor_sync(0xffffffffu, acc3, 16);

    // all 32 lanes store: lanes 0-15 write s0/s1, lanes 16-31 write s2/s3
    {
        float* orow = out + (size_t)row * 64;
        int  l15  = lane & 15;
        bool lo16 = lane < 16;
        int  off  = lo16 ? l15 : (32 + l15);
        orow[off]      = lo16 ? acc0 : acc2;
        orow[off + 16] = lo16 ? acc1 : acc3;
    }
}

// Generic fallback (any N): one 64-thread block per row, direct evaluation.
__global__ void radial_aev_generic(const float* __restrict__ dmat,
                                   const int*   __restrict__ species,
                                   float*       __restrict__ out,
                                   int N, int rows)
{
    int row = blockIdx.x;
    if (row >= rows) return;
    int t = threadIdx.x;            // 64 threads: s = t>>4, p = t&15
    int s = t >> 4, p = t & 15;
    float shf = fmaf((float)p, 0.26875f, 0.9f);
    const float* drow = dmat + (size_t)row * N;
    const int*   srow = species + (size_t)(row / N) * N;
    float acc = 0.0f;
    for (int j = 0; j < N; j++) {
        float d = drow[j];
        if (d > 0.0f && d < RCUT && (srow[j] - 1) == s) {
            float fc = 0.5f * __cosf(d * PI_RC) + 0.5f;
            float tt = d - shf;
            acc += __expf(-16.0f * tt * tt) * fc;
        }
    }
    out[(size_t)row * 64 + t] = acc;
}

extern "C" void kernel_launch(void* const* d_in, const int* in_sizes, int n_in,
                              void* d_out, int out_size)
{
    const float* dmat    = (const float*)d_in[0];
    const int*   species = (const int*)d_in[1];
    float*       out     = (float*)d_out;

    const int rows = in_sizes[1];                 // B*N
    const int N    = in_sizes[0] / in_sizes[1];   // N

    if (N == 256 && (rows & (WPB - 1)) == 0 && (rows & 255) == 0) {
        radial_aev_256<<<rows / WPB, 32 * WPB>>>(dmat, species, out);
    } else {
        radial_aev_generic<<<rows, 64>>>(dmat, species, out, N, rows);
    }
}